// round 6
// baseline (speedup 1.0000x reference)
#include <cuda_runtime.h>
#include <cuda_bf16.h>
#include <cstdint>

// out[b,i,:] = sum_j exp(q_i . k_j) * v_j   (B=4, S=4096, D=64, fp32)
// mma.sync bf16 split-precision, FA-style register reuse.
// R6: exp+split fused into GEMM2 (no phi/plo arrays -> no reg spills).

#define S_LEN 4096
#define B_SZ  4
#define DD    64
#define TQ    128
#define TK    128
#define NTH   256
#define NTILES (S_LEN / TK)

#define PITCH 144              // 64 bf16 + 8B pad
#define KBUF  (TK * PITCH)     // 18432 per hi/lo buffer

#define SM_K  0                       // K hi @0, K lo @KBUF
#define SM_V  (2 * KBUF)              // V hi, V lo
#define SM_TOTAL (4 * KBUF)           // 73728 B

#define LOG2E 1.4426950408889634f

// ---------------- PTX helpers ----------------
__device__ __forceinline__ uint32_t smem_u32(const void* p) {
    uint32_t a;
    asm("{ .reg .u64 t; cvta.to.shared.u64 t, %1; cvt.u32.u64 %0, t; }" : "=r"(a) : "l"(p));
    return a;
}
#define LDMX4(r, a) \
    asm volatile("ldmatrix.sync.aligned.m8n8.x4.shared.b16 {%0,%1,%2,%3}, [%4];" \
        : "=r"((r)[0]), "=r"((r)[1]), "=r"((r)[2]), "=r"((r)[3]) : "r"(a))
#define LDMX4T(r, a) \
    asm volatile("ldmatrix.sync.aligned.m8n8.x4.trans.shared.b16 {%0,%1,%2,%3}, [%4];" \
        : "=r"((r)[0]), "=r"((r)[1]), "=r"((r)[2]), "=r"((r)[3]) : "r"(a))
#define MMA(c, av, bv) \
    asm volatile("mma.sync.aligned.m16n8k16.row.col.f32.bf16.bf16.f32 " \
        "{%0,%1,%2,%3}, {%4,%5,%6,%7}, {%8,%9}, {%0,%1,%2,%3};" \
        : "+f"((c)[0]), "+f"((c)[1]), "+f"((c)[2]), "+f"((c)[3]) \
        : "r"((av)[0]), "r"((av)[1]), "r"((av)[2]), "r"((av)[3]), \
          "r"((bv)[0]), "r"((bv)[1]))

__device__ __forceinline__ float ex2f(float x) {
    float r;
    asm("ex2.approx.ftz.f32 %0, %1;" : "=f"(r) : "f"(x));
    return r;
}
__device__ __forceinline__ void split_pack(float x, float y, uint32_t& hi, uint32_t& lo) {
    __nv_bfloat16 xh = __float2bfloat16(x), yh = __float2bfloat16(y);
    float xr = x - __bfloat162float(xh);
    float yr = y - __bfloat162float(yh);
    __nv_bfloat16 xl = __float2bfloat16(xr), yl = __float2bfloat16(yr);
    hi = ((uint32_t)__bfloat16_as_ushort(yh) << 16) | (uint32_t)__bfloat16_as_ushort(xh);
    lo = ((uint32_t)__bfloat16_as_ushort(yl) << 16) | (uint32_t)__bfloat16_as_ushort(xl);
}

// LDG a [128 x 64] fp32 tile into 8 float4 regs per thread
__device__ __forceinline__ void ldg_tile(const float* __restrict__ g, float4 r[8], int tid) {
    #pragma unroll
    for (int i = 0; i < 8; ++i) {
        int f = tid + i * NTH;
        int row = f >> 4, d0 = (f & 15) << 2;
        r[i] = *(const float4*)&g[(size_t)row * DD + d0];
    }
}
// split+store those regs to hi/lo bf16 smem (pitch 144), optional scale
__device__ __forceinline__ void sts_tile(const float4 r[8], char* smhi, int tid, float scale) {
    #pragma unroll
    for (int i = 0; i < 8; ++i) {
        int f = tid + i * NTH;
        int row = f >> 4, d0 = (f & 15) << 2;
        uint32_t h0, l0, h1, l1;
        split_pack(r[i].x * scale, r[i].y * scale, h0, l0);
        split_pack(r[i].z * scale, r[i].w * scale, h1, l1);
        int off = row * PITCH + d0 * 2;
        *(uint2*)(smhi + off)        = make_uint2(h0, h1);
        *(uint2*)(smhi + KBUF + off) = make_uint2(l0, l1);
    }
}

__global__ void __launch_bounds__(NTH, 1)
fa_fa6_kernel(const float* __restrict__ q, const float* __restrict__ k,
              const float* __restrict__ v, float* __restrict__ out)
{
    extern __shared__ char smem[];
    const uint32_t sb = smem_u32(smem);
    const int tid  = threadIdx.x;
    const int wid  = tid >> 5;
    const int lane = tid & 31;
    const int b  = blockIdx.y;
    const int q0 = blockIdx.x * TQ;

    const float* Qg = q + ((size_t)b * S_LEN + q0) * DD;
    const float* Kg = k + (size_t)b * S_LEN * DD;
    const float* Vg = v + (size_t)b * S_LEN * DD;
    float*       Og = out + ((size_t)b * S_LEN + q0) * DD;

    // ---- prologue: stage Q (x log2e) through K buffer, grab persistent A-frags ----
    float4 pf[8];
    ldg_tile(Qg, pf, tid);
    sts_tile(pf, smem + SM_K, tid, LOG2E);
    __syncthreads();

    uint32_t qhi[4][4], qlo[4][4];
    {
        const uint32_t aQ = sb + SM_K +
            (uint32_t)((wid * 16 + (lane & 15)) * PITCH + (lane >> 4) * 16);
        #pragma unroll
        for (int ks = 0; ks < 4; ++ks) {
            LDMX4(qhi[ks], aQ + ks * 32);
            LDMX4(qlo[ks], aQ + KBUF + ks * 32);
        }
    }
    __syncthreads();

    // stage K0, V0
    ldg_tile(Kg, pf, tid);
    sts_tile(pf, smem + SM_K, tid, 1.0f);
    ldg_tile(Vg, pf, tid);
    sts_tile(pf, smem + SM_V, tid, 1.0f);
    __syncthreads();

    // per-lane B-operand ldmatrix bases
    const uint32_t bK = sb + SM_K +
        (uint32_t)(( ((lane >> 4) & 1) * 8 + (lane & 7) ) * PITCH + ((lane >> 3) & 1) * 16);
    const uint32_t bV = sb + SM_V +
        (uint32_t)(( ((lane >> 3) & 1) * 8 + (lane & 7) ) * PITCH + (((lane >> 4) & 1) * 8) * 2);

    float acc2[8][4];
    #pragma unroll
    for (int ni = 0; ni < 8; ++ni)
        #pragma unroll
        for (int e = 0; e < 4; ++e) acc2[ni][e] = 0.0f;

    for (int t = 0; t < NTILES; ++t) {
        const int tn = (t + 1 < NTILES) ? t + 1 : 0;   // clamped prefetch

        // ---- prefetch K(t+1); GEMM1(t): S(16 x 128 per warp) ----
        ldg_tile(Kg + (size_t)(tn * TK) * DD, pf, tid);

        float acc1[16][4];
        #pragma unroll
        for (int n = 0; n < 16; ++n)
            #pragma unroll
            for (int e = 0; e < 4; ++e) acc1[n][e] = 0.0f;

        #pragma unroll
        for (int ks = 0; ks < 4; ++ks) {
            #pragma unroll
            for (int p = 0; p < 8; ++p) {     // n-pairs: blocks 2p, 2p+1
                uint32_t bb = bK + (uint32_t)(p * 16 * PITCH + ks * 32);
                uint32_t bhi[4], blo[4];
                LDMX4(bhi, bb);
                LDMX4(blo, bb + KBUF);
                MMA(acc1[2*p],   qhi[ks], bhi);
                MMA(acc1[2*p],   qhi[ks], blo);
                MMA(acc1[2*p],   qlo[ks], bhi);
                MMA(acc1[2*p+1], qhi[ks], bhi + 2);
                MMA(acc1[2*p+1], qhi[ks], blo + 2);
                MMA(acc1[2*p+1], qlo[ks], bhi + 2);
            }
        }
        __syncthreads();                      // all warps done reading K(t)

        // K(t+1) visible at next barrier; V(t+1) prefetch under GEMM2
        sts_tile(pf, smem + SM_K, tid, 1.0f);
        ldg_tile(Vg + (size_t)(tn * TK) * DD, pf, tid);

        // ---- GEMM2(t): O += P @ V with exp+split fused per key-step ----
        #pragma unroll
        for (int ks = 0; ks < 8; ++ks) {
            // convert S n-blocks 2ks, 2ks+1 -> P A-frags (8 regs, short-lived)
            uint32_t phi[4], plo[4];
            {
                float e0 = ex2f(acc1[2*ks][0]);
                float e1 = ex2f(acc1[2*ks][1]);
                float e2 = ex2f(acc1[2*ks][2]);
                float e3 = ex2f(acc1[2*ks][3]);
                split_pack(e0, e1, phi[0], plo[0]);
                split_pack(e2, e3, phi[1], plo[1]);
                float f0 = ex2f(acc1[2*ks+1][0]);
                float f1 = ex2f(acc1[2*ks+1][1]);
                float f2 = ex2f(acc1[2*ks+1][2]);
                float f3 = ex2f(acc1[2*ks+1][3]);
                split_pack(f0, f1, phi[2], plo[2]);
                split_pack(f2, f3, phi[3], plo[3]);
            }
            #pragma unroll
            for (int p = 0; p < 4; ++p) {     // d-pairs: blocks 2p, 2p+1
                uint32_t bb = bV + (uint32_t)(ks * 16 * PITCH + p * 32);
                uint32_t bhi[4], blo[4];
                LDMX4T(bhi, bb);
                LDMX4T(blo, bb + KBUF);
                MMA(acc2[2*p],   phi, bhi);
                MMA(acc2[2*p],   phi, blo);
                MMA(acc2[2*p],   plo, bhi);
                MMA(acc2[2*p+1], phi, bhi + 2);
                MMA(acc2[2*p+1], phi, blo + 2);
                MMA(acc2[2*p+1], plo, bhi + 2);
            }
        }
        __syncthreads();                      // all warps done reading V(t); K(t+1) visible
        sts_tile(pf, smem + SM_V, tid, 1.0f); // V(t+1); visible at next barrier
    }

    // ---- epilogue: O rows wid*16 .. +16 ----
    #pragma unroll
    for (int ni = 0; ni < 8; ++ni) {
        int r = wid * 16 + (lane >> 2);
        int c = ni * 8 + (lane & 3) * 2;
        *(float2*)&Og[(size_t)r * DD + c]       = make_float2(acc2[ni][0], acc2[ni][1]);
        *(float2*)&Og[(size_t)(r + 8) * DD + c] = make_float2(acc2[ni][2], acc2[ni][3]);
    }
}

extern "C" void kernel_launch(void* const* d_in, const int* in_sizes, int n_in,
                              void* d_out, int out_size)
{
    const float* q = (const float*)d_in[0];
    const float* k = (const float*)d_in[1];
    const float* v = (const float*)d_in[2];
    float* out = (float*)d_out;
    (void)in_sizes; (void)n_in; (void)out_size;

    cudaFuncSetAttribute(fa_fa6_kernel,
                         cudaFuncAttributeMaxDynamicSharedMemorySize, SM_TOTAL);
    dim3 grid(S_LEN / TQ, B_SZ);   // 32 x 4 = 128 CTAs, one wave
    fa_fa6_kernel<<<grid, NTH, SM_TOTAL>>>(q, k, v, out);
}

// round 7
// speedup vs baseline: 1.0012x; 1.0012x over previous
#include <cuda_runtime.h>
#include <cuda_bf16.h>
#include <cstdint>

// out[b,i,:] = sum_j exp(q_i . k_j) * v_j   (B=4, S=4096, D=64, fp32)
// mma.sync bf16 split-precision, FA-style register P.
// R7: warps split 4M x 2N -> B-operand LDSM halved; GEMM2 split-K over
//     key halves with one smem reduction at the end.

#define S_LEN 4096
#define B_SZ  4
#define DD    64
#define TQ    128
#define TK    128
#define NTH   256
#define NTILES (S_LEN / TK)

#define PITCH 144              // 64 bf16 + 8B pad
#define QB    (TK * PITCH)     // 18432 per hi/lo buffer

#define SM_Q  0                // Q hi @0, lo @QB
#define SM_K  (2 * QB)         // K hi, lo
#define SM_V  (4 * QB)         // V hi, lo
#define SM_TOTAL (6 * QB)      // 110592 B
#define RED_PITCH 72           // fp32 reduction buffer pitch (floats)
// reduction buffer aliases SM_Q: 128*72*4 = 36864 = 2*QB exactly

#define LOG2E 1.4426950408889634f

__device__ __forceinline__ uint32_t smem_u32(const void* p) {
    uint32_t a;
    asm("{ .reg .u64 t; cvta.to.shared.u64 t, %1; cvt.u32.u64 %0, t; }" : "=r"(a) : "l"(p));
    return a;
}
#define LDMX4(r, a) \
    asm volatile("ldmatrix.sync.aligned.m8n8.x4.shared.b16 {%0,%1,%2,%3}, [%4];" \
        : "=r"((r)[0]), "=r"((r)[1]), "=r"((r)[2]), "=r"((r)[3]) : "r"(a))
#define LDMX4T(r, a) \
    asm volatile("ldmatrix.sync.aligned.m8n8.x4.trans.shared.b16 {%0,%1,%2,%3}, [%4];" \
        : "=r"((r)[0]), "=r"((r)[1]), "=r"((r)[2]), "=r"((r)[3]) : "r"(a))
#define MMA(c, av, bv) \
    asm volatile("mma.sync.aligned.m16n8k16.row.col.f32.bf16.bf16.f32 " \
        "{%0,%1,%2,%3}, {%4,%5,%6,%7}, {%8,%9}, {%0,%1,%2,%3};" \
        : "+f"((c)[0]), "+f"((c)[1]), "+f"((c)[2]), "+f"((c)[3]) \
        : "r"((av)[0]), "r"((av)[1]), "r"((av)[2]), "r"((av)[3]), \
          "r"((bv)[0]), "r"((bv)[1]))

__device__ __forceinline__ float ex2f(float x) {
    float r;
    asm("ex2.approx.ftz.f32 %0, %1;" : "=f"(r) : "f"(x));
    return r;
}
__device__ __forceinline__ void split_pack(float x, float y, uint32_t& hi, uint32_t& lo) {
    __nv_bfloat16 xh = __float2bfloat16(x), yh = __float2bfloat16(y);
    float xr = x - __bfloat162float(xh);
    float yr = y - __bfloat162float(yh);
    __nv_bfloat16 xl = __float2bfloat16(xr), yl = __float2bfloat16(yr);
    hi = ((uint32_t)__bfloat16_as_ushort(yh) << 16) | (uint32_t)__bfloat16_as_ushort(xh);
    lo = ((uint32_t)__bfloat16_as_ushort(yl) << 16) | (uint32_t)__bfloat16_as_ushort(xl);
}
__device__ __forceinline__ void ldg_tile(const float* __restrict__ g, float4 r[8], int tid) {
    #pragma unroll
    for (int i = 0; i < 8; ++i) {
        int f = tid + i * NTH;
        int row = f >> 4, d0 = (f & 15) << 2;
        r[i] = *(const float4*)&g[(size_t)row * DD + d0];
    }
}
__device__ __forceinline__ void sts_tile(const float4 r[8], char* smhi, int tid, float scale) {
    #pragma unroll
    for (int i = 0; i < 8; ++i) {
        int f = tid + i * NTH;
        int row = f >> 4, d0 = (f & 15) << 2;
        uint32_t h0, l0, h1, l1;
        split_pack(r[i].x * scale, r[i].y * scale, h0, l0);
        split_pack(r[i].z * scale, r[i].w * scale, h1, l1);
        int off = row * PITCH + d0 * 2;
        *(uint2*)(smhi + off)      = make_uint2(h0, h1);
        *(uint2*)(smhi + QB + off) = make_uint2(l0, l1);
    }
}

__global__ void __launch_bounds__(NTH, 1)
fa_fa7_kernel(const float* __restrict__ q, const float* __restrict__ k,
              const float* __restrict__ v, float* __restrict__ out)
{
    extern __shared__ char smem[];
    const uint32_t sb = smem_u32(smem);
    const int tid  = threadIdx.x;
    const int wid  = tid >> 5;
    const int lane = tid & 31;
    const int m    = wid & 3;    // M-group: rows m*32 .. +31
    const int g    = wid >> 2;   // N-group: S cols / keys g*64 .. +63
    const int b  = blockIdx.y;
    const int q0 = blockIdx.x * TQ;

    const float* Qg = q + ((size_t)b * S_LEN + q0) * DD;
    const float* Kg = k + (size_t)b * S_LEN * DD;
    const float* Vg = v + (size_t)b * S_LEN * DD;
    float*       Og = out + ((size_t)b * S_LEN + q0) * DD;

    // ---- prologue: stage Q (x log2e), K0, V0 ----
    float4 pf[8];
    ldg_tile(Qg, pf, tid);
    sts_tile(pf, smem + SM_Q, tid, LOG2E);
    ldg_tile(Kg, pf, tid);
    sts_tile(pf, smem + SM_K, tid, 1.0f);
    ldg_tile(Vg, pf, tid);
    sts_tile(pf, smem + SM_V, tid, 1.0f);
    __syncthreads();

    // per-lane ldmatrix bases
    const uint32_t aQ = sb + SM_Q +
        (uint32_t)((m * 32 + (lane & 15)) * PITCH + (lane >> 4) * 16);
    const uint32_t bK = sb + SM_K +
        (uint32_t)((g * 64 + ((lane >> 4) & 1) * 8 + (lane & 7)) * PITCH +
                   ((lane >> 3) & 1) * 16);
    const uint32_t bV = sb + SM_V +
        (uint32_t)((g * 64 + ((lane >> 3) & 1) * 8 + (lane & 7)) * PITCH +
                   (((lane >> 4) & 1) * 8) * 2);

    float acc2[2][8][4];   // O partial: rows m*32+mi*16, d 0..63, keys g*64..
    #pragma unroll
    for (int mi = 0; mi < 2; ++mi)
        #pragma unroll
        for (int n = 0; n < 8; ++n)
            #pragma unroll
            for (int e = 0; e < 4; ++e) acc2[mi][n][e] = 0.0f;

    for (int t = 0; t < NTILES; ++t) {
        const int tn = (t + 1 < NTILES) ? t + 1 : 0;

        // ---- prefetch K(t+1); GEMM1(t): S(32 x 64 per warp) ----
        ldg_tile(Kg + (size_t)(tn * TK) * DD, pf, tid);

        float acc1[2][8][4];
        #pragma unroll
        for (int mi = 0; mi < 2; ++mi)
            #pragma unroll
            for (int n = 0; n < 8; ++n)
                #pragma unroll
                for (int e = 0; e < 4; ++e) acc1[mi][n][e] = 0.0f;

        #pragma unroll
        for (int ks = 0; ks < 4; ++ks) {
            uint32_t qh[2][4], ql[2][4];
            #pragma unroll
            for (int mi = 0; mi < 2; ++mi) {
                uint32_t a = aQ + (uint32_t)(mi * 16 * PITCH + ks * 32);
                LDMX4(qh[mi], a);
                LDMX4(ql[mi], a + QB);
            }
            #pragma unroll
            for (int p = 0; p < 4; ++p) {     // n-pairs within warp's 64 cols
                uint32_t bb = bK + (uint32_t)(p * 16 * PITCH + ks * 32);
                uint32_t bhi[4], blo[4];
                LDMX4(bhi, bb);
                LDMX4(blo, bb + QB);
                #pragma unroll
                for (int mi = 0; mi < 2; ++mi) {
                    MMA(acc1[mi][2*p],   qh[mi], bhi);
                    MMA(acc1[mi][2*p],   qh[mi], blo);
                    MMA(acc1[mi][2*p],   ql[mi], bhi);
                    MMA(acc1[mi][2*p+1], qh[mi], bhi + 2);
                    MMA(acc1[mi][2*p+1], qh[mi], blo + 2);
                    MMA(acc1[mi][2*p+1], ql[mi], bhi + 2);
                }
            }
        }
        __syncthreads();                      // all warps done reading K(t)

        sts_tile(pf, smem + SM_K, tid, 1.0f); // K(t+1)
        ldg_tile(Vg + (size_t)(tn * TK) * DD, pf, tid);

        // ---- GEMM2(t): O += P @ V, exp+split fused per key-step ----
        #pragma unroll
        for (int ks = 0; ks < 4; ++ks) {      // warp's 64 keys, 16 at a time
            uint32_t phi[2][4], plo[2][4];
            #pragma unroll
            for (int mi = 0; mi < 2; ++mi) {
                float e0 = ex2f(acc1[mi][2*ks][0]);
                float e1 = ex2f(acc1[mi][2*ks][1]);
                float e2 = ex2f(acc1[mi][2*ks][2]);
                float e3 = ex2f(acc1[mi][2*ks][3]);
                split_pack(e0, e1, phi[mi][0], plo[mi][0]);
                split_pack(e2, e3, phi[mi][1], plo[mi][1]);
                float f0 = ex2f(acc1[mi][2*ks+1][0]);
                float f1 = ex2f(acc1[mi][2*ks+1][1]);
                float f2 = ex2f(acc1[mi][2*ks+1][2]);
                float f3 = ex2f(acc1[mi][2*ks+1][3]);
                split_pack(f0, f1, phi[mi][2], plo[mi][2]);
                split_pack(f2, f3, phi[mi][3], plo[mi][3]);
            }
            #pragma unroll
            for (int p = 0; p < 4; ++p) {     // d-pairs
                uint32_t bb = bV + (uint32_t)(ks * 16 * PITCH + p * 32);
                uint32_t bhi[4], blo[4];
                LDMX4T(bhi, bb);
                LDMX4T(blo, bb + QB);
                #pragma unroll
                for (int mi = 0; mi < 2; ++mi) {
                    MMA(acc2[mi][2*p],   phi[mi], bhi);
                    MMA(acc2[mi][2*p],   phi[mi], blo);
                    MMA(acc2[mi][2*p],   plo[mi], bhi);
                    MMA(acc2[mi][2*p+1], phi[mi], bhi + 2);
                    MMA(acc2[mi][2*p+1], phi[mi], blo + 2);
                    MMA(acc2[mi][2*p+1], plo[mi], bhi + 2);
                }
            }
        }
        __syncthreads();                      // all warps done reading V(t)
        sts_tile(pf, smem + SM_V, tid, 1.0f); // V(t+1)
    }

    // ---- split-K reduction: g==1 partials -> smem (aliases Q), g==0 adds ----
    float* red = (float*)(smem + SM_Q);
    if (g == 1) {
        #pragma unroll
        for (int mi = 0; mi < 2; ++mi)
            #pragma unroll
            for (int n = 0; n < 8; ++n) {
                int r = m * 32 + mi * 16 + (lane >> 2);
                int c = n * 8 + (lane & 3) * 2;
                *(float2*)&red[r * RED_PITCH + c] =
                    make_float2(acc2[mi][n][0], acc2[mi][n][1]);
                *(float2*)&red[(r + 8) * RED_PITCH + c] =
                    make_float2(acc2[mi][n][2], acc2[mi][n][3]);
            }
    }
    __syncthreads();
    if (g == 0) {
        #pragma unroll
        for (int mi = 0; mi < 2; ++mi)
            #pragma unroll
            for (int n = 0; n < 8; ++n) {
                int r = m * 32 + mi * 16 + (lane >> 2);
                int c = n * 8 + (lane & 3) * 2;
                float2 p0 = *(const float2*)&red[r * RED_PITCH + c];
                float2 p1 = *(const float2*)&red[(r + 8) * RED_PITCH + c];
                *(float2*)&Og[(size_t)r * DD + c] =
                    make_float2(acc2[mi][n][0] + p0.x, acc2[mi][n][1] + p0.y);
                *(float2*)&Og[(size_t)(r + 8) * DD + c] =
                    make_float2(acc2[mi][n][2] + p1.x, acc2[mi][n][3] + p1.y);
            }
    }
}

extern "C" void kernel_launch(void* const* d_in, const int* in_sizes, int n_in,
                              void* d_out, int out_size)
{
    const float* q = (const float*)d_in[0];
    const float* k = (const float*)d_in[1];
    const float* v = (const float*)d_in[2];
    float* out = (float*)d_out;
    (void)in_sizes; (void)n_in; (void)out_size;

    cudaFuncSetAttribute(fa_fa7_kernel,
                         cudaFuncAttributeMaxDynamicSharedMemorySize, SM_TOTAL);
    dim3 grid(S_LEN / TQ, B_SZ);   // 32 x 4 = 128 CTAs, one wave
    fa_fa7_kernel<<<grid, NTH, SM_TOTAL>>>(q, k, v, out);
}